// round 11
// baseline (speedup 1.0000x reference)
#include <cuda_runtime.h>
#include <cuda_bf16.h>
#include <cuda_fp16.h>
#include <cstdint>
#include <math.h>

#define TB 2
#define TT 2048
#define TC 1024
#define TH 16
#define HD 64
#define BT (TB*TT)     // 4096 rows
#define KG 1024        // GEMM K

// ---------------- scratch (allocation-free) ----------------
__device__ __half g_xh[(size_t)BT * TC];
__device__ __half g_yh[(size_t)BT * TC];
__device__ __half g_wah[(size_t)3 * TC * TC];
__device__ __half g_wph[(size_t)TC * TC];
// attention operands, pre-split bf16 (per (b,h)): Q/K [t][d], V^T [d][t]
#define BH_ELEMS ((size_t)TB * TH * TT * HD)
__device__ __nv_bfloat16 g_Qh[BH_ELEMS], g_Ql[BH_ELEMS];
__device__ __nv_bfloat16 g_Kh[BH_ELEMS], g_Kl[BH_ELEMS];
__device__ __nv_bfloat16 g_VTh[BH_ELEMS], g_VTl[BH_ELEMS];

__device__ __forceinline__ uint32_t smem_u32(const void* p) {
    uint32_t a;
    asm("{ .reg .u64 t; cvta.to.shared.u64 t, %1; cvt.u32.u64 %0, t; }" : "=r"(a) : "l"(p));
    return a;
}
__device__ __forceinline__ void ldmx4(uint32_t* r, uint32_t addr) {
    asm volatile("ldmatrix.sync.aligned.m8n8.x4.shared.b16 {%0,%1,%2,%3}, [%4];"
        : "=r"(r[0]), "=r"(r[1]), "=r"(r[2]), "=r"(r[3]) : "r"(addr));
}
__device__ __forceinline__ void mma16816h(float* c, const uint32_t* a, const uint32_t* b) {
    asm volatile("mma.sync.aligned.m16n8k16.row.col.f32.f16.f16.f32 "
        "{%0,%1,%2,%3}, {%4,%5,%6,%7}, {%8,%9}, {%0,%1,%2,%3};"
        : "+f"(c[0]), "+f"(c[1]), "+f"(c[2]), "+f"(c[3])
        : "r"(a[0]), "r"(a[1]), "r"(a[2]), "r"(a[3]), "r"(b[0]), "r"(b[1]));
}
__device__ __forceinline__ void mma16816(float* c, const uint32_t* a, const uint32_t* b) {
    asm volatile("mma.sync.aligned.m16n8k16.row.col.f32.bf16.bf16.f32 "
        "{%0,%1,%2,%3}, {%4,%5,%6,%7}, {%8,%9}, {%0,%1,%2,%3};"
        : "+f"(c[0]), "+f"(c[1]), "+f"(c[2]), "+f"(c[3])
        : "r"(a[0]), "r"(a[1]), "r"(a[2]), "r"(a[3]), "r"(b[0]), "r"(b[1]));
}
__device__ __forceinline__ void cp_async16(uint32_t smem, const void* g) {
    asm volatile("cp.async.cg.shared.global [%0], [%1], 16;" :: "r"(smem), "l"(g));
}
#define CP_COMMIT() asm volatile("cp.async.commit_group;" ::: "memory")
#define CP_WAIT(n)  asm volatile("cp.async.wait_group %0;" :: "n"(n) : "memory")

__device__ __forceinline__ void cvt_hl(float f0, float f1, uint32_t& h, uint32_t& l) {
    __nv_bfloat162 hb = __floats2bfloat162_rn(f0, f1);
    float2 hf = __bfloat1622float2(hb);
    __nv_bfloat162 lb = __floats2bfloat162_rn(f0 - hf.x, f1 - hf.y);
    h = *(uint32_t*)&hb;
    l = *(uint32_t*)&lb;
}

// ---------------- convert kernels ----------------
__global__ void conv_half(const float4* __restrict__ s, __half2* __restrict__ d, int n4) {
    int i = blockIdx.x * 256 + threadIdx.x;
    if (i >= n4) return;
    float4 f = s[i];
    d[2 * i]     = __floats2half2_rn(f.x, f.y);
    d[2 * i + 1] = __floats2half2_rn(f.z, f.w);
}

__global__ void conv_wt_half(const float* __restrict__ W, __half* __restrict__ d, int N) {
    __shared__ float t[32][33];
    const int k0 = blockIdx.y * 32, n0 = blockIdx.x * 32;
    const int tx = threadIdx.x, ty = threadIdx.y;
#pragma unroll
    for (int i = 0; i < 32; i += 8)
        t[ty + i][tx] = W[(size_t)(k0 + ty + i) * N + n0 + tx];
    __syncthreads();
#pragma unroll
    for (int i = 0; i < 32; i += 8)
        d[(size_t)(n0 + ty + i) * KG + k0 + tx] = __float2half(t[tx][ty + i]);
}

// ---------------- fp16 HMMA GEMM, templated epilogue ----------------
// MODE 0: write fp32 C.   MODE 1: split-qkv epilogue -> g_Qh/Ql/Kh/Kl/VTh/VTl.
#define BM 128
#define BN 256
#define BK 32
#define LDA 40
#define A_BYTES (BM * LDA * 2)
#define B_BYTES (BN * LDA * 2)
#define STG_STRIDE (A_BYTES + B_BYTES)
#define NSTG 4
#define GEMM_SMEM (NSTG * STG_STRIDE)

template <int MODE>
__global__ __launch_bounds__(512, 1)
void gemm_hmma(const __half* __restrict__ A,
               const __half* __restrict__ B,
               float* __restrict__ C, int N) {
    extern __shared__ __half smb[];
    const uint32_t sbase = smem_u32(smb);
    const int tid = threadIdx.x, wid = tid >> 5, lane = tid & 31;
    const int m0 = blockIdx.y * BM, n0 = blockIdx.x * BN;
    const int wm0 = (wid >> 3) * 64;
    const int wn0 = (wid & 7) * 32;

    float acc[4][4][4];
#pragma unroll
    for (int f = 0; f < 4; f++)
#pragma unroll
        for (int j = 0; j < 4; j++)
#pragma unroll
            for (int e = 0; e < 4; e++) acc[f][j][e] = 0.f;

    const uint4* Ag = (const uint4*)A;
    const uint4* Bg = (const uint4*)B;
    const int KU = KG / 8;
    const int NST = KG / BK;

    const int arow = tid >> 2, ach = tid & 3;
    const int brow0 = tid >> 2, brow1 = (tid + 512) >> 2;

    auto issue = [&](int s) {
        const int kc = s * (BK / 8);
        const uint32_t As = sbase + (uint32_t)(s & (NSTG - 1)) * STG_STRIDE;
        const uint32_t Bs = As + A_BYTES;
        cp_async16(As + (uint32_t)((arow * LDA + ach * 8) * 2),
                   &Ag[(size_t)(m0 + arow) * KU + kc + ach]);
        cp_async16(Bs + (uint32_t)((brow0 * LDA + ach * 8) * 2),
                   &Bg[(size_t)(n0 + brow0) * KU + kc + ach]);
        cp_async16(Bs + (uint32_t)((brow1 * LDA + ach * 8) * 2),
                   &Bg[(size_t)(n0 + brow1) * KU + kc + ach]);
    };

    const int a_r = lane & 15, a_c = (lane >> 4) * 8;
    const int b_n = ((lane >> 4) & 1) * 8 + (lane & 7);
    const int b_k = ((lane >> 3) & 1) * 8;

#pragma unroll
    for (int s = 0; s < NSTG - 1; ++s) { issue(s); CP_COMMIT(); }

#pragma unroll 1
    for (int s = 0; s < NST; ++s) {
        CP_WAIT(NSTG - 2);
        __syncthreads();

        const uint32_t As0 = sbase + (uint32_t)(s & (NSTG - 1)) * STG_STRIDE;
        const uint32_t Bs0 = As0 + A_BYTES;

#pragma unroll
        for (int ks = 0; ks < 2; ++ks) {
            const int k0 = ks * 16;
            uint32_t afr[4][4], bfr[4][2];
#pragma unroll
            for (int f = 0; f < 4; f++)
                ldmx4(afr[f], As0 + (uint32_t)((wm0 + f * 16 + a_r) * 80 + (k0 + a_c) * 2));
#pragma unroll
            for (int p = 0; p < 2; p++) {
                uint32_t r[4];
                ldmx4(r, Bs0 + (uint32_t)((wn0 + p * 16 + b_n) * 80 + (k0 + b_k) * 2));
                bfr[2 * p][0] = r[0]; bfr[2 * p][1] = r[1];
                bfr[2 * p + 1][0] = r[2]; bfr[2 * p + 1][1] = r[3];
            }
#pragma unroll
            for (int f = 0; f < 4; f++)
#pragma unroll
                for (int j = 0; j < 4; j++)
                    mma16816h(acc[f][j], afr[f], bfr[j]);
        }

        if (s + NSTG - 1 < NST) issue(s + NSTG - 1);
        CP_COMMIT();
    }

    const int er = lane >> 2, ec = (lane & 3) * 2;
    if (MODE == 0) {
#pragma unroll
        for (int f = 0; f < 4; f++) {
            const int row = m0 + wm0 + f * 16 + er;
#pragma unroll
            for (int j = 0; j < 4; j++) {
                const int col = n0 + wn0 + j * 8 + ec;
                *(float2*)&C[(size_t)row * N + col]       = make_float2(acc[f][j][0], acc[f][j][1]);
                *(float2*)&C[(size_t)(row + 8) * N + col] = make_float2(acc[f][j][2], acc[f][j][3]);
            }
        }
    } else {
        // split-qkv epilogue: rows are (b*2048 + t); cols map to {Q,K,V} x head x d
#pragma unroll
        for (int f = 0; f < 4; f++) {
            const int row = m0 + wm0 + f * 16 + er;
            const int b = row >> 11, t = row & 2047;   // row+8 stays in same b (128 | 2048)
#pragma unroll
            for (int j = 0; j < 4; j++) {
                const int col = n0 + wn0 + j * 8 + ec;  // uniform sec/head across the pair
                const int sec = col >> 10;
                const int hh = (col >> 6) & 15;
                const int d = col & 63;
                const int bh = b * TH + hh;
                if (sec < 2) {
                    uint32_t h0, l0, h1, l1;
                    cvt_hl(acc[f][j][0], acc[f][j][1], h0, l0);   // row t,   d..d+1
                    cvt_hl(acc[f][j][2], acc[f][j][3], h1, l1);   // row t+8, d..d+1
                    const size_t o = ((size_t)bh * TT + t) * HD + d;
                    if (sec == 0) {
                        *(uint32_t*)&g_Qh[o] = h0;           *(uint32_t*)&g_Ql[o] = l0;
                        *(uint32_t*)&g_Qh[o + 8 * HD] = h1;  *(uint32_t*)&g_Ql[o + 8 * HD] = l1;
                    } else {
                        *(uint32_t*)&g_Kh[o] = h0;           *(uint32_t*)&g_Kl[o] = l0;
                        *(uint32_t*)&g_Kh[o + 8 * HD] = h1;  *(uint32_t*)&g_Kl[o + 8 * HD] = l1;
                    }
                } else {
                    // V transposed: VT[d][t], scalar bf16 stores
                    const size_t o = ((size_t)bh * HD + d) * TT + t;
                    float v;
                    __nv_bfloat16 hb;
                    v = acc[f][j][0]; hb = __float2bfloat16(v);
                    g_VTh[o] = hb;            g_VTl[o] = __float2bfloat16(v - __bfloat162float(hb));
                    v = acc[f][j][2]; hb = __float2bfloat16(v);
                    g_VTh[o + 8] = hb;        g_VTl[o + 8] = __float2bfloat16(v - __bfloat162float(hb));
                    v = acc[f][j][1]; hb = __float2bfloat16(v);
                    g_VTh[o + TT] = hb;       g_VTl[o + TT] = __float2bfloat16(v - __bfloat162float(hb));
                    v = acc[f][j][3]; hb = __float2bfloat16(v);
                    g_VTh[o + TT + 8] = hb;   g_VTl[o + TT + 8] = __float2bfloat16(v - __bfloat162float(hb));
                }
            }
        }
    }
}

// ---------------- flash attention (unchanged from R9, passing) ----------------
#define AP 72
#define QBYTES (128 * AP * 2)
#define TILE_B (64 * AP * 2)
#define KV_STAGE (4 * TILE_B)
#define ATT_SMEM (2 * QBYTES + 2 * KV_STAGE)  // 110592

__global__ __launch_bounds__(256, 1)
void attn_mma(__half* __restrict__ yh) {
    extern __shared__ char smc[];
    const uint32_t sb = smem_u32(smc);
    const uint32_t sQh = sb, sQl = sb + QBYTES;
    const uint32_t sKV = sb + 2 * QBYTES;

    const int qb = blockIdx.x, h = blockIdx.y, b = blockIdx.z;
    const int q0 = qb * 128;
    const int tid = threadIdx.x, wid = tid >> 5, lane = tid & 31;
    const int wq = wid * 16;
    const size_t bh = (size_t)(b * TH + h);

    const __nv_bfloat16* gQh = g_Qh + (bh * TT + q0) * HD;
    const __nv_bfloat16* gQl = g_Ql + (bh * TT + q0) * HD;
    const __nv_bfloat16* gKh = g_Kh + bh * TT * HD;
    const __nv_bfloat16* gKl = g_Kl + bh * TT * HD;
    const __nv_bfloat16* gVTh = g_VTh + bh * HD * TT;
    const __nv_bfloat16* gVTl = g_VTl + bh * HD * TT;

    const int a_r = lane & 15, a_c = (lane >> 4) * 8;
    const int b_n = ((lane >> 4) & 1) * 8 + (lane & 7);
    const int b_k = ((lane >> 3) & 1) * 8;

#pragma unroll
    for (int p = 0; p < 8; ++p) {
        int i = tid + p * 256;
        int hl = i >> 10, rem = i & 1023, r = rem >> 3, ch = rem & 7;
        const __nv_bfloat16* src = (hl ? gQl : gQh) + (size_t)r * HD + ch * 8;
        cp_async16((hl ? sQl : sQh) + (uint32_t)(r * 144 + ch * 16), src);
    }

    auto issue_kv = [&](int kt) {
        const int k0 = kt * 64;
        const uint32_t stg = sKV + (uint32_t)(kt & 1) * KV_STAGE;
#pragma unroll
        for (int p = 0; p < 8; ++p) {
            int i = tid + p * 256;
            int buf = i >> 9, rem = i & 511, r = rem >> 3, ch = rem & 7;
            const __nv_bfloat16* src;
            if (buf == 0)      src = gKh  + (size_t)(k0 + r) * HD + ch * 8;
            else if (buf == 1) src = gKl  + (size_t)(k0 + r) * HD + ch * 8;
            else if (buf == 2) src = gVTh + (size_t)r * TT + k0 + ch * 8;
            else               src = gVTl + (size_t)r * TT + k0 + ch * 8;
            cp_async16(stg + (uint32_t)(buf * TILE_B + r * 144 + ch * 16), src);
        }
    };

    const int nkt = qb * 2 + 2;
    issue_kv(0);
    CP_COMMIT();

    float mrow[2] = { -1e30f, -1e30f }, lrow[2] = { 0.f, 0.f };
    float oacc[8][4];
#pragma unroll
    for (int nb = 0; nb < 8; ++nb)
#pragma unroll
        for (int e = 0; e < 4; ++e) oacc[nb][e] = 0.f;

    for (int kt = 0; kt < nkt; ++kt) {
        const int k0 = kt * 64;
        if (kt + 1 < nkt) { issue_kv(kt + 1); CP_COMMIT(); CP_WAIT(1); }
        else              { CP_WAIT(0); }
        __syncthreads();

        if (k0 <= q0 + wq + 15) {
            const uint32_t stg = sKV + (uint32_t)(kt & 1) * KV_STAGE;
            const uint32_t Kh0 = stg, Kl0 = stg + TILE_B;
            const uint32_t Vh0 = stg + 2 * TILE_B, Vl0 = stg + 3 * TILE_B;

            float sacc[8][4];
#pragma unroll
            for (int nb = 0; nb < 8; ++nb)
#pragma unroll
                for (int e = 0; e < 4; ++e) sacc[nb][e] = 0.f;

#pragma unroll
            for (int ks = 0; ks < 4; ++ks) {
                const int kk = ks * 16;
                uint32_t qh[4], ql[4];
                const uint32_t qoff = (uint32_t)((wq + a_r) * 144 + (kk + a_c) * 2);
                ldmx4(qh, sQh + qoff);
                ldmx4(ql, sQl + qoff);
#pragma unroll
                for (int p = 0; p < 4; ++p) {
                    uint32_t kh[4], kl[4];
                    const uint32_t boff = (uint32_t)((p * 16 + b_n) * 144 + (kk + b_k) * 2);
                    ldmx4(kh, Kh0 + boff);
                    ldmx4(kl, Kl0 + boff);
                    mma16816(sacc[2 * p],     qh, &kh[0]);
                    mma16816(sacc[2 * p + 1], qh, &kh[2]);
                    mma16816(sacc[2 * p],     qh, &kl[0]);
                    mma16816(sacc[2 * p + 1], qh, &kl[2]);
                    mma16816(sacc[2 * p],     ql, &kh[0]);
                    mma16816(sacc[2 * p + 1], ql, &kh[2]);
                }
            }

            const int grow0 = q0 + wq + (lane >> 2);
            const bool dmask = (k0 + 63) > (q0 + wq);
            float mloc0 = -1e30f, mloc1 = -1e30f;
#pragma unroll
            for (int nb = 0; nb < 8; ++nb) {
                const int col = k0 + nb * 8 + (lane & 3) * 2;
                float s0 = sacc[nb][0] * 0.125f, s1 = sacc[nb][1] * 0.125f;
                float s2 = sacc[nb][2] * 0.125f, s3 = sacc[nb][3] * 0.125f;
                if (dmask) {
                    if (col     > grow0)     s0 = -1e30f;
                    if (col + 1 > grow0)     s1 = -1e30f;
                    if (col     > grow0 + 8) s2 = -1e30f;
                    if (col + 1 > grow0 + 8) s3 = -1e30f;
                }
                sacc[nb][0] = s0; sacc[nb][1] = s1; sacc[nb][2] = s2; sacc[nb][3] = s3;
                mloc0 = fmaxf(mloc0, fmaxf(s0, s1));
                mloc1 = fmaxf(mloc1, fmaxf(s2, s3));
            }
            mloc0 = fmaxf(mloc0, __shfl_xor_sync(0xffffffffu, mloc0, 1));
            mloc0 = fmaxf(mloc0, __shfl_xor_sync(0xffffffffu, mloc0, 2));
            mloc1 = fmaxf(mloc1, __shfl_xor_sync(0xffffffffu, mloc1, 1));
            mloc1 = fmaxf(mloc1, __shfl_xor_sync(0xffffffffu, mloc1, 2));
            const float mn0 = fmaxf(mrow[0], mloc0);
            const float mn1 = fmaxf(mrow[1], mloc1);

            float sum0 = 0.f, sum1 = 0.f;
#pragma unroll
            for (int nb = 0; nb < 8; ++nb) {
                float e0 = __expf(sacc[nb][0] - mn0), e1 = __expf(sacc[nb][1] - mn0);
                float e2 = __expf(sacc[nb][2] - mn1), e3 = __expf(sacc[nb][3] - mn1);
                sacc[nb][0] = e0; sacc[nb][1] = e1; sacc[nb][2] = e2; sacc[nb][3] = e3;
                sum0 += e0 + e1; sum1 += e2 + e3;
            }
            sum0 += __shfl_xor_sync(0xffffffffu, sum0, 1);
            sum0 += __shfl_xor_sync(0xffffffffu, sum0, 2);
            sum1 += __shfl_xor_sync(0xffffffffu, sum1, 1);
            sum1 += __shfl_xor_sync(0xffffffffu, sum1, 2);

            const float sc0 = __expf(mrow[0] - mn0);
            const float sc1 = __expf(mrow[1] - mn1);
            lrow[0] = lrow[0] * sc0 + sum0;
            lrow[1] = lrow[1] * sc1 + sum1;
            mrow[0] = mn0; mrow[1] = mn1;
#pragma unroll
            for (int nb = 0; nb < 8; ++nb) {
                oacc[nb][0] *= sc0; oacc[nb][1] *= sc0;
                oacc[nb][2] *= sc1; oacc[nb][3] *= sc1;
            }

            uint32_t pfh[4][4], pfl[4][4];
#pragma unroll
            for (int c = 0; c < 4; ++c) {
                cvt_hl(sacc[2 * c][0],     sacc[2 * c][1],     pfh[c][0], pfl[c][0]);
                cvt_hl(sacc[2 * c][2],     sacc[2 * c][3],     pfh[c][1], pfl[c][1]);
                cvt_hl(sacc[2 * c + 1][0], sacc[2 * c + 1][1], pfh[c][2], pfl[c][2]);
                cvt_hl(sacc[2 * c + 1][2], sacc[2 * c + 1][3], pfh[c][3], pfl[c][3]);
            }

#pragma unroll
            for (int c = 0; c < 4; ++c) {
#pragma unroll
                for (int p = 0; p < 4; ++p) {
                    uint32_t vh[4], vl[4];
                    const uint32_t boff = (uint32_t)((p * 16 + b_n) * 144 + (c * 16 + b_k) * 2);
                    ldmx4(vh, Vh0 + boff);
                    ldmx4(vl, Vl0 + boff);
                    mma16816(oacc[2 * p],     pfh[c], &vh[0]);
                    mma16816(oacc[2 * p + 1], pfh[c], &vh[2]);
                    mma16816(oacc[2 * p],     pfl[c], &vh[0]);
                    mma16816(oacc[2 * p + 1], pfl[c], &vh[2]);
                    mma16816(oacc[2 * p],     pfh[c], &vl[0]);
                    mma16816(oacc[2 * p + 1], pfh[c], &vl[2]);
                }
            }
        }
        __syncthreads();
    }

    const float inv0 = 1.f / lrow[0], inv1 = 1.f / lrow[1];
    const int row0 = q0 + wq + (lane >> 2);
    const size_t rb0 = (size_t)(b * TT + row0) * TC + h * HD;
    const size_t rb1 = rb0 + (size_t)8 * TC;
#pragma unroll
    for (int nb = 0; nb < 8; ++nb) {
        const int d0 = nb * 8 + (lane & 3) * 2;
        __half2 v0 = __floats2half2_rn(oacc[nb][0] * inv0, oacc[nb][1] * inv0);
        __half2 v1 = __floats2half2_rn(oacc[nb][2] * inv1, oacc[nb][3] * inv1);
        *(__half2*)&yh[rb0 + d0] = v0;
        *(__half2*)&yh[rb1 + d0] = v1;
    }
}

// ---------------------------------------------------------------------------
extern "C" void kernel_launch(void* const* d_in, const int* in_sizes, int n_in,
                              void* d_out, int out_size) {
    const float* x  = (const float*)d_in[0];
    const float* Wa = (const float*)d_in[1];
    const float* Wp = (const float*)d_in[2];
    float* out = (float*)d_out;

    __half *xh, *yh, *wah, *wph;
    cudaGetSymbolAddress((void**)&xh, g_xh);
    cudaGetSymbolAddress((void**)&yh, g_yh);
    cudaGetSymbolAddress((void**)&wah, g_wah);
    cudaGetSymbolAddress((void**)&wph, g_wph);

    cudaFuncSetAttribute(gemm_hmma<0>, cudaFuncAttributeMaxDynamicSharedMemorySize, GEMM_SMEM);
    cudaFuncSetAttribute(gemm_hmma<1>, cudaFuncAttributeMaxDynamicSharedMemorySize, GEMM_SMEM);
    cudaFuncSetAttribute(attn_mma, cudaFuncAttributeMaxDynamicSharedMemorySize, ATT_SMEM);

    // x -> fp16
    {
        int n4 = BT * TC / 4;
        conv_half<<<(n4 + 255) / 256, 256>>>((const float4*)x, (__half2*)xh, n4);
    }
    // weights -> fp16 transposed
    {
        dim3 gw(3 * TC / 32, TC / 32);
        conv_wt_half<<<gw, dim3(32, 8)>>>(Wa, wah, 3 * TC);
        dim3 gp(TC / 32, TC / 32);
        conv_wt_half<<<gp, dim3(32, 8)>>>(Wp, wph, TC);
    }
    // qkv GEMM with fused split-qkv epilogue (writes g_Qh/Ql/Kh/Kl/VTh/VTl)
    {
        dim3 g(3 * TC / BN, BT / BM);
        gemm_hmma<1><<<g, 512, GEMM_SMEM>>>(xh, wah, nullptr, 3 * TC);
    }
    // attention -> y fp16
    {
        dim3 ga(TT / 128, TH, TB);
        attn_mma<<<ga, 256, ATT_SMEM>>>(yh);
    }
    // out = y @ W_proj
    {
        dim3 g(TC / BN, BT / BM);
        gemm_hmma<0><<<g, 512, GEMM_SMEM>>>(yh, wph, out, TC);
    }
}